// round 3
// baseline (speedup 1.0000x reference)
#include <cuda_runtime.h>
#include <cuda_fp16.h>
#include <cstdint>

// ---------------------------------------------------------------------------
// EdgeDense: z = x @ W + b  (N x 32, stored fp16), then
//            out[e] = w_e * (z[rows[e]] + z[cols[e]])   (fp32 out)
// N_NODES = 100000, IN = 128, OUT = 32, E = 1.6M
// ---------------------------------------------------------------------------

#define MAX_NODES 100000
#define IN_F 128
#define OUT_F 32
#define GEMM_BLOCK 256

// z in fp16: 100000 * 32 * 2B = 6.4 MB (L2-resident). Device global.
__device__ __half2 g_zh[(size_t)MAX_NODES * (OUT_F / 2)];
// Index-dtype flag: 1 => indices are int64, 0 => indices are int32.
__device__ int g_idx64;

typedef unsigned long long ull_t;

#define FMA_F32X2(d, a, b, c) \
    asm("fma.rn.f32x2 %0, %1, %2, %3;" : "=l"(d) : "l"(a), "l"(b), "l"(c))
#define PACK_DUP_F32X2(d, s) \
    asm("mov.b64 %0, {%1, %2};" : "=l"(d) : "f"(s), "f"(s))
#define UNPACK_F32X2(lo, hi, in) \
    asm("mov.b64 {%0, %1}, %2;" : "=f"(lo), "=f"(hi) : "l"(in))

// ---------------------------------------------------------------------------
// GEMM: 8 threads per node (lane oq = tid&7 computes outputs 4*oq..4*oq+3).
// All 8 lanes of a node read the SAME x float4 -> broadcast LDG (4 distinct
// lines per warp instr instead of 32 -> 8x fewer L1 wavefronts than the
// one-node-per-thread layout). W rows live in smem; consecutive floats are
// read as ulonglong2 = ready-made f32x2 operand pairs (no pack movs).
// Block 0 also classifies the edge-index dtype (JAX x64-off hazard):
// int32 data read as int64 words is >= 2^32 whenever the odd word != 0 --
// unambiguous over 256 words for uniform indices in [0, 100000).
// ---------------------------------------------------------------------------
__global__ __launch_bounds__(GEMM_BLOCK)
void gemm_kernel(const float4* __restrict__ x4,
                 const float*  __restrict__ W,    // [128][32] row-major
                 const float*  __restrict__ b,    // [32]
                 __half2* __restrict__ zh,
                 int n_nodes,
                 const long long* __restrict__ idx_probe) {
    __shared__ float sW[IN_F * OUT_F];
    __shared__ int s_bad;

    int tid = threadIdx.x;

    #pragma unroll
    for (int i = tid; i < IN_F * OUT_F; i += GEMM_BLOCK) sW[i] = W[i];
    if (blockIdx.x == 0 && tid == 0) s_bad = 0;
    __syncthreads();

    if (blockIdx.x == 0) {
        long long v = idx_probe[tid];
        if (v < 0 || v >= (long long)n_nodes) atomicOr(&s_bad, 1);
    }

    int nl = tid >> 3;          // local node 0..31
    int oq = tid & 7;           // output quad 0..7
    int node = blockIdx.x * (GEMM_BLOCK / 8) + nl;

    // Two f32x2 accumulators = outputs [4*oq, 4*oq+4), seeded with bias.
    const ull_t* b2 = (const ull_t*)b;
    ull_t acc0 = __ldg(&b2[2 * oq + 0]);
    ull_t acc1 = __ldg(&b2[2 * oq + 1]);

    if (node < n_nodes) {
        const float4* xr = x4 + (size_t)node * (IN_F / 4);
        #pragma unroll 8
        for (int kk = 0; kk < IN_F / 4; kk++) {
            float4 xv = __ldg(&xr[kk]);   // broadcast across the 8-lane group
            float xs[4] = {xv.x, xv.y, xv.z, xv.w};
            #pragma unroll
            for (int j = 0; j < 4; j++) {
                int k = 4 * kk + j;
                const ulonglong2* wp =
                    reinterpret_cast<const ulonglong2*>(sW + k * OUT_F + oq * 4);
                ulonglong2 wv = *wp;      // LDS.128, conflict-free
                ull_t ss;
                PACK_DUP_F32X2(ss, xs[j]);
                FMA_F32X2(acc0, ss, wv.x, acc0);
                FMA_F32X2(acc1, ss, wv.y, acc1);
            }
        }

        // 4 fp32 -> 4 fp16 -> 8B store (warp stores 4 contiguous 64B rows).
        float f0, f1, f2, f3;
        UNPACK_F32X2(f0, f1, acc0);
        UNPACK_F32X2(f2, f3, acc1);
        __half2 h0 = __floats2half2_rn(f0, f1);
        __half2 h1 = __floats2half2_rn(f2, f3);
        uint2 hv;
        hv.x = *reinterpret_cast<unsigned*>(&h0);
        hv.y = *reinterpret_cast<unsigned*>(&h1);
        reinterpret_cast<uint2*>(zh)[(size_t)node * 8 + oq] = hv;
    }

    if (blockIdx.x == 0) {
        __syncthreads();
        if (tid == 0) g_idx64 = s_bad ? 0 : 1;
    }
}

// ---------------------------------------------------------------------------
// Edge kernel: 4 threads per edge-slot, each thread processes TWO edges
// (m and m + E/2) for 2x memory-level parallelism. Indices are loaded as
// int32 low words (valid for both int32 and little-endian int64 buffers:
// element stride selected by g_idx64). Gathers are uint4 over 64B fp16 rows;
// output stores coalesced, streaming (__stcs).
// ---------------------------------------------------------------------------
__global__ __launch_bounds__(256)
void edge_kernel(const __half2* __restrict__ zh,
                 const int* __restrict__ rows,
                 const int* __restrict__ cols,
                 const float* __restrict__ vals,
                 float4* __restrict__ out,
                 int n_edges) {
    int gid = blockIdx.x * blockDim.x + threadIdx.x;
    int E2 = (n_edges + 1) >> 1;
    int m = gid >> 2;
    int c = gid & 3;
    if (m >= E2) return;

    int sh = g_idx64;           // 0: int32 layout, 1: int64 (read low word)
    int e0 = m;
    int e1 = m + E2;
    bool has1 = (e1 < n_edges);

    int r0 = __ldcs(&rows[e0 << sh]);
    int c0 = __ldcs(&cols[e0 << sh]);
    float w0 = __ldcs(&vals[e0]);
    int r1 = 0, c1 = 0;
    float w1 = 0.f;
    if (has1) {
        r1 = __ldcs(&rows[e1 << sh]);
        c1 = __ldcs(&cols[e1 << sh]);
        w1 = __ldcs(&vals[e1]);
    }

    const uint4* zb = reinterpret_cast<const uint4*>(zh);
    // row -> 4 uint4; this thread takes quad c.
    uint4 a0 = __ldg(&zb[(size_t)r0 * 4 + c]);
    uint4 d0 = __ldg(&zb[(size_t)c0 * 4 + c]);
    uint4 a1, d1;
    if (has1) {
        a1 = __ldg(&zb[(size_t)r1 * 4 + c]);
        d1 = __ldg(&zb[(size_t)c1 * 4 + c]);
    }

    // --- edge e0 ---
    {
        float4 o0, o1;
        float2 fa, fd;
        fa = __half22float2(*reinterpret_cast<__half2*>(&a0.x));
        fd = __half22float2(*reinterpret_cast<__half2*>(&d0.x));
        o0.x = w0 * (fa.x + fd.x);  o0.y = w0 * (fa.y + fd.y);
        fa = __half22float2(*reinterpret_cast<__half2*>(&a0.y));
        fd = __half22float2(*reinterpret_cast<__half2*>(&d0.y));
        o0.z = w0 * (fa.x + fd.x);  o0.w = w0 * (fa.y + fd.y);
        fa = __half22float2(*reinterpret_cast<__half2*>(&a0.z));
        fd = __half22float2(*reinterpret_cast<__half2*>(&d0.z));
        o1.x = w0 * (fa.x + fd.x);  o1.y = w0 * (fa.y + fd.y);
        fa = __half22float2(*reinterpret_cast<__half2*>(&a0.w));
        fd = __half22float2(*reinterpret_cast<__half2*>(&d0.w));
        o1.z = w0 * (fa.x + fd.x);  o1.w = w0 * (fa.y + fd.y);
        float4* ob = out + (size_t)e0 * 8 + c * 2;
        __stcs(ob + 0, o0);
        __stcs(ob + 1, o1);
    }
    // --- edge e1 ---
    if (has1) {
        float4 o0, o1;
        float2 fa, fd;
        fa = __half22float2(*reinterpret_cast<__half2*>(&a1.x));
        fd = __half22float2(*reinterpret_cast<__half2*>(&d1.x));
        o0.x = w1 * (fa.x + fd.x);  o0.y = w1 * (fa.y + fd.y);
        fa = __half22float2(*reinterpret_cast<__half2*>(&a1.y));
        fd = __half22float2(*reinterpret_cast<__half2*>(&d1.y));
        o0.z = w1 * (fa.x + fd.x);  o0.w = w1 * (fa.y + fd.y);
        fa = __half22float2(*reinterpret_cast<__half2*>(&a1.z));
        fd = __half22float2(*reinterpret_cast<__half2*>(&d1.z));
        o1.x = w1 * (fa.x + fd.x);  o1.y = w1 * (fa.y + fd.y);
        fa = __half22float2(*reinterpret_cast<__half2*>(&a1.w));
        fd = __half22float2(*reinterpret_cast<__half2*>(&d1.w));
        o1.z = w1 * (fa.x + fd.x);  o1.w = w1 * (fa.y + fd.y);
        float4* ob = out + (size_t)e1 * 8 + c * 2;
        __stcs(ob + 0, o0);
        __stcs(ob + 1, o1);
    }
}

// ---------------------------------------------------------------------------
// Launch. Inputs (metadata order): x, W, b, edge_rows, edge_cols, edge_vals.
// ---------------------------------------------------------------------------
extern "C" void kernel_launch(void* const* d_in, const int* in_sizes, int n_in,
                              void* d_out, int out_size) {
    const float4* x4   = (const float4*)d_in[0];
    const float*  W    = (const float*)d_in[1];
    const float*  b    = (const float*)d_in[2];
    const void*   rows = d_in[3];
    const void*   cols = d_in[4];
    const float*  vals = (const float*)d_in[5];
    float4* out = (float4*)d_out;

    int n_nodes = in_sizes[0] / IN_F;
    int n_edges = in_sizes[3];

    __half2* zh = nullptr;
    cudaGetSymbolAddress((void**)&zh, g_zh);

    // 1) z = x @ W + b  (+ index-dtype probe in block 0)
    int nodes_per_block = GEMM_BLOCK / 8;
    int gemm_blocks = (n_nodes + nodes_per_block - 1) / nodes_per_block;
    gemm_kernel<<<gemm_blocks, GEMM_BLOCK>>>(
        x4, W, b, zh, n_nodes, (const long long*)rows);

    // 2) out[e] = w_e * (z[r] + z[c]), two edges per thread
    int E2 = (n_edges + 1) >> 1;
    long long total = (long long)E2 * 4;
    int edge_blocks = (int)((total + 255) / 256);
    edge_kernel<<<edge_blocks, 256>>>(zh, (const int*)rows, (const int*)cols,
                                      vals, out, n_edges);
}

// round 4
// speedup vs baseline: 1.2981x; 1.2981x over previous
#include <cuda_runtime.h>
#include <cuda_fp16.h>
#include <cstdint>

// ---------------------------------------------------------------------------
// EdgeDense: z = x @ W + b  (N x 32, stored fp16), then
//            out[e] = w_e * (z[rows[e]] + z[cols[e]])   (fp32 out)
// N_NODES = 100000, IN = 128, OUT = 32, E = 1.6M
// ---------------------------------------------------------------------------

#define MAX_NODES 100000
#define IN_F 128
#define OUT_F 32
#define GEMM_BLOCK 128          // threads = nodes per block

// z in fp16: 100000 * 32 * 2B = 6.4 MB (L2-resident). Device global.
__device__ __half2 g_zh[(size_t)MAX_NODES * (OUT_F / 2)];
// Index-dtype flag: 1 => indices are int64, 0 => indices are int32.
__device__ int g_idx64;

typedef unsigned long long ull_t;

#define FMA_F32X2(d, a, b, c) \
    asm("fma.rn.f32x2 %0, %1, %2, %3;" : "=l"(d) : "l"(a), "l"(b), "l"(c))
#define PACK_DUP_F32X2(d, s) \
    asm("mov.b64 %0, {%1, %2};" : "=l"(d) : "f"(s), "f"(s))
#define UNPACK_F32X2(lo, hi, in) \
    asm("mov.b64 {%0, %1}, %2;" : "=f"(lo), "=f"(hi) : "l"(in))

// ---------------------------------------------------------------------------
// GEMM: one node per thread, 16 f32x2 accumulators.
// x is staged through smem in 4 k-chunks of 32 (128B per node per chunk,
// line-aligned: staging LDGs touch 4 lines/instr instead of 32). Padded
// stride 36 floats => conflict-free LDS.128 for both staging stores and
// compute reads (bank of lane t = (4t + 4k) mod 32, distinct per 8-lane
// phase). W rows are read as ulonglong2 = ready-made f32x2 operand pairs.
// Block 0 also classifies the edge-index dtype (JAX x64-off hazard):
// int32 data read as int64 words is >= 2^32 whenever the odd word != 0 --
// unambiguous over 128 words for uniform indices in [0, 100000).
// ---------------------------------------------------------------------------
#define X_STRIDE 36             // 32 + 4 pad floats

__global__ __launch_bounds__(GEMM_BLOCK)
void gemm_kernel(const float4* __restrict__ x4,
                 const float*  __restrict__ W,    // [128][32] row-major
                 const float*  __restrict__ b,    // [32]
                 __half2* __restrict__ zh,
                 int n_nodes,
                 const long long* __restrict__ idx_probe) {
    __shared__ float sW[IN_F * OUT_F];            // 16 KB
    __shared__ float sx[GEMM_BLOCK * X_STRIDE];   // 18 KB
    __shared__ int s_bad;

    int tid = threadIdx.x;
    int base = blockIdx.x * GEMM_BLOCK;
    int node = base + tid;

    #pragma unroll
    for (int i = tid; i < IN_F * OUT_F; i += GEMM_BLOCK) sW[i] = W[i];
    if (blockIdx.x == 0 && tid == 0) s_bad = 0;

    if (blockIdx.x == 0) {
        long long v = idx_probe[tid];
        if (v < 0 || v >= (long long)n_nodes) atomicOr(&s_bad, 1);
    }

    // 16 packed f32x2 accumulators seeded with bias pairs.
    ull_t acc[OUT_F / 2];
    const ull_t* b2 = (const ull_t*)b;
    #pragma unroll
    for (int o = 0; o < OUT_F / 2; o++) acc[o] = __ldg(&b2[o]);

    #pragma unroll
    for (int chunk = 0; chunk < 4; chunk++) {
        __syncthreads();
        // Stage 128 nodes x 32 k-values (128B/node, line-aligned, coalesced:
        // 8 consecutive threads read one full 128B row-chunk).
        #pragma unroll
        for (int j = 0; j < 8; j++) {
            int i = j * GEMM_BLOCK + tid;
            int n = i >> 3;
            int q = i & 7;
            int gn = base + n;
            float4 v = make_float4(0.f, 0.f, 0.f, 0.f);
            if (gn < n_nodes)
                v = __ldg(&x4[(size_t)gn * (IN_F / 4) + chunk * 8 + q]);
            *reinterpret_cast<float4*>(&sx[n * X_STRIDE + q * 4]) = v;
        }
        __syncthreads();

        #pragma unroll
        for (int kk = 0; kk < 8; kk++) {
            float4 xv = *reinterpret_cast<const float4*>(
                &sx[tid * X_STRIDE + kk * 4]);
            float xs[4] = {xv.x, xv.y, xv.z, xv.w};
            #pragma unroll
            for (int j = 0; j < 4; j++) {
                int k = chunk * 32 + kk * 4 + j;
                const ulonglong2* wp =
                    reinterpret_cast<const ulonglong2*>(sW + k * OUT_F);
                ull_t ss;
                PACK_DUP_F32X2(ss, xs[j]);
                #pragma unroll
                for (int u = 0; u < 8; u++) {
                    ulonglong2 wv = wp[u];        // broadcast LDS.128
                    FMA_F32X2(acc[2 * u + 0], ss, wv.x, acc[2 * u + 0]);
                    FMA_F32X2(acc[2 * u + 1], ss, wv.y, acc[2 * u + 1]);
                }
            }
        }
    }

    if (node < n_nodes) {
        // 32 fp32 -> 32 fp16, store 64B row as 4 STG.128.
        __half2 h[OUT_F / 2];
        #pragma unroll
        for (int o = 0; o < OUT_F / 2; o++) {
            float lo, hi;
            UNPACK_F32X2(lo, hi, acc[o]);
            h[o] = __floats2half2_rn(lo, hi);
        }
        uint4* zrow = reinterpret_cast<uint4*>(zh + (size_t)node * (OUT_F / 2));
        const uint4* hv = reinterpret_cast<const uint4*>(h);
        #pragma unroll
        for (int q = 0; q < 4; q++) zrow[q] = hv[q];
    }

    if (blockIdx.x == 0) {
        __syncthreads();
        if (tid == 0) g_idx64 = s_bad ? 0 : 1;
    }
}

// ---------------------------------------------------------------------------
// Edge kernel: 8 lanes per edge, uint2 (8B = 4 fp16) gathers. Each gather
// warp-instruction touches only 4 distinct z rows (4 lines) instead of 8,
// shifting L1tex wavefronts from the 2.07 cyc within-instruction replay rate
// toward the 1.0 cyc cross-instruction rate. Each thread processes two edges
// (m and m + E/2) for MLP. Index loads are lane-redundant but
// address-uniform (broadcast => no extra wavefronts). Per edge the 8 lanes
// store one contiguous 128B line via a single STG.128 each.
// ---------------------------------------------------------------------------
__global__ __launch_bounds__(256)
void edge_kernel(const __half2* __restrict__ zh,
                 const int* __restrict__ rows,
                 const int* __restrict__ cols,
                 const float* __restrict__ vals,
                 float4* __restrict__ out,
                 int n_edges) {
    int gid = blockIdx.x * blockDim.x + threadIdx.x;
    int E2 = (n_edges + 1) >> 1;
    int m = gid >> 3;
    int c = gid & 7;
    if (m >= E2) return;

    int sh = g_idx64;           // 0: int32 layout, 1: int64 (read low word)
    int e0 = m;
    int e1 = m + E2;
    bool has1 = (e1 < n_edges);

    int r0 = __ldcs(&rows[e0 << sh]);
    int c0 = __ldcs(&cols[e0 << sh]);
    float w0 = __ldcs(&vals[e0]);
    int r1 = 0, c1 = 0;
    float w1 = 0.f;
    if (has1) {
        r1 = __ldcs(&rows[e1 << sh]);
        c1 = __ldcs(&cols[e1 << sh]);
        w1 = __ldcs(&vals[e1]);
    }

    const uint2* zb = reinterpret_cast<const uint2*>(zh);   // 8 uint2 per row
    uint2 a0 = __ldg(&zb[(size_t)r0 * 8 + c]);
    uint2 d0 = __ldg(&zb[(size_t)c0 * 8 + c]);
    uint2 a1 = make_uint2(0, 0), d1 = make_uint2(0, 0);
    if (has1) {
        a1 = __ldg(&zb[(size_t)r1 * 8 + c]);
        d1 = __ldg(&zb[(size_t)c1 * 8 + c]);
    }

    // --- edge e0: 4 outputs for this lane ---
    {
        float2 fa0 = __half22float2(*reinterpret_cast<__half2*>(&a0.x));
        float2 fd0 = __half22float2(*reinterpret_cast<__half2*>(&d0.x));
        float2 fa1 = __half22float2(*reinterpret_cast<__half2*>(&a0.y));
        float2 fd1 = __half22float2(*reinterpret_cast<__half2*>(&d0.y));
        float4 o;
        o.x = w0 * (fa0.x + fd0.x);
        o.y = w0 * (fa0.y + fd0.y);
        o.z = w0 * (fa1.x + fd1.x);
        o.w = w0 * (fa1.y + fd1.y);
        __stcs(&out[(size_t)e0 * 8 + c], o);
    }
    // --- edge e1 ---
    if (has1) {
        float2 fa0 = __half22float2(*reinterpret_cast<__half2*>(&a1.x));
        float2 fd0 = __half22float2(*reinterpret_cast<__half2*>(&d1.x));
        float2 fa1 = __half22float2(*reinterpret_cast<__half2*>(&a1.y));
        float2 fd1 = __half22float2(*reinterpret_cast<__half2*>(&d1.y));
        float4 o;
        o.x = w1 * (fa0.x + fd0.x);
        o.y = w1 * (fa0.y + fd0.y);
        o.z = w1 * (fa1.x + fd1.x);
        o.w = w1 * (fa1.y + fd1.y);
        __stcs(&out[(size_t)e1 * 8 + c], o);
    }
}

// ---------------------------------------------------------------------------
// Launch. Inputs (metadata order): x, W, b, edge_rows, edge_cols, edge_vals.
// ---------------------------------------------------------------------------
extern "C" void kernel_launch(void* const* d_in, const int* in_sizes, int n_in,
                              void* d_out, int out_size) {
    const float4* x4   = (const float4*)d_in[0];
    const float*  W    = (const float*)d_in[1];
    const float*  b    = (const float*)d_in[2];
    const void*   rows = d_in[3];
    const void*   cols = d_in[4];
    const float*  vals = (const float*)d_in[5];
    float4* out = (float4*)d_out;

    int n_nodes = in_sizes[0] / IN_F;
    int n_edges = in_sizes[3];

    __half2* zh = nullptr;
    cudaGetSymbolAddress((void**)&zh, g_zh);

    // 1) z = x @ W + b  (+ index-dtype probe in block 0)
    int gemm_blocks = (n_nodes + GEMM_BLOCK - 1) / GEMM_BLOCK;
    gemm_kernel<<<gemm_blocks, GEMM_BLOCK>>>(
        x4, W, b, zh, n_nodes, (const long long*)rows);

    // 2) out[e] = w_e * (z[r] + z[c]), two edges per thread, 8 lanes/edge
    int E2 = (n_edges + 1) >> 1;
    long long total = (long long)E2 * 8;
    int edge_blocks = (int)((total + 255) / 256);
    edge_kernel<<<edge_blocks, 256>>>(zh, (const int*)rows, (const int*)cols,
                                      vals, out, n_edges);
}

// round 5
// speedup vs baseline: 1.4183x; 1.0926x over previous
#include <cuda_runtime.h>
#include <cuda_fp16.h>
#include <cstdint>

// ---------------------------------------------------------------------------
// EdgeDense: z = x @ W + b  (N x 32, stored fp16), then
//            out[e] = w_e * (z[rows[e]] + z[cols[e]])   (fp32 out)
// N_NODES = 100000, IN = 128, OUT = 32, E = 1.6M
// ---------------------------------------------------------------------------

#define MAX_NODES 100000
#define IN_F 128
#define OUT_F 32
#define GEMM_BLOCK 128          // threads per block
#define NPB 256                 // nodes per block (2 per thread)

// z in fp16: 100000 * 32 * 2B = 6.4 MB (L2-resident). Device global.
__device__ __half2 g_zh[(size_t)MAX_NODES * (OUT_F / 2)];
// Index-dtype flag: 1 => indices are int64, 0 => indices are int32.
__device__ int g_idx64;

typedef unsigned long long ull_t;

#define FMA_F32X2(d, a, b, c) \
    asm("fma.rn.f32x2 %0, %1, %2, %3;" : "=l"(d) : "l"(a), "l"(b), "l"(c))
#define PACK_DUP_F32X2(d, s) \
    asm("mov.b64 %0, {%1, %2};" : "=l"(d) : "f"(s), "f"(s))
#define UNPACK_F32X2(lo, hi, in) \
    asm("mov.b64 {%0, %1}, %2;" : "=f"(lo), "=f"(hi) : "l"(in))

// ---------------------------------------------------------------------------
// GEMM: TWO nodes per thread (tid and tid+128), 2 x 16 f32x2 accumulators.
// Each W row is loaded from smem ONCE per k and reused for both nodes:
// FMA:LDS ratio 4:1 (was 2:1), W-LDS per node halved.
// x staged through smem in 4 k-chunks of 32 floats/node (128B, line-aligned:
// staging LDGs touch 4 lines/instr). Padded stride 36 => conflict-free
// LDS.128. Block 0 also classifies the edge-index dtype (JAX x64-off
// hazard): int32 data read as int64 words is >= 2^32 whenever the odd word
// != 0 -- unambiguous over 128 words for uniform indices in [0, 100000).
// ---------------------------------------------------------------------------
#define X_STRIDE 36             // 32 + 4 pad floats

__global__ __launch_bounds__(GEMM_BLOCK)
void gemm_kernel(const float4* __restrict__ x4,
                 const float*  __restrict__ W,    // [128][32] row-major
                 const float*  __restrict__ b,    // [32]
                 __half2* __restrict__ zh,
                 int n_nodes,
                 const long long* __restrict__ idx_probe) {
    __shared__ float sW[IN_F * OUT_F];            // 16 KB
    __shared__ float sx[NPB * X_STRIDE];          // 36 KB
    __shared__ int s_bad;

    int tid = threadIdx.x;
    int base = blockIdx.x * NPB;

    #pragma unroll
    for (int i = tid; i < IN_F * OUT_F; i += GEMM_BLOCK) sW[i] = W[i];
    if (blockIdx.x == 0 && tid == 0) s_bad = 0;

    if (blockIdx.x == 0) {
        long long v = idx_probe[tid];
        if (v < 0 || v >= (long long)n_nodes) atomicOr(&s_bad, 1);
    }

    // 2 x 16 packed f32x2 accumulators seeded with bias pairs.
    ull_t acc0[OUT_F / 2], acc1[OUT_F / 2];
    const ull_t* b2 = (const ull_t*)b;
    #pragma unroll
    for (int o = 0; o < OUT_F / 2; o++) {
        ull_t bv = __ldg(&b2[o]);
        acc0[o] = bv;
        acc1[o] = bv;
    }

    int n0 = tid;               // local node ids
    int n1 = tid + GEMM_BLOCK;

    #pragma unroll
    for (int chunk = 0; chunk < 4; chunk++) {
        __syncthreads();
        // Stage 256 nodes x 32 k-values (128B/node/chunk, coalesced:
        // 8 consecutive threads fetch one full 128B row-chunk).
        #pragma unroll
        for (int j = 0; j < 16; j++) {
            int i = j * GEMM_BLOCK + tid;
            int n = i >> 3;
            int q = i & 7;
            int gn = base + n;
            float4 v = make_float4(0.f, 0.f, 0.f, 0.f);
            if (gn < n_nodes)
                v = __ldg(&x4[(size_t)gn * (IN_F / 4) + chunk * 8 + q]);
            *reinterpret_cast<float4*>(&sx[n * X_STRIDE + q * 4]) = v;
        }
        __syncthreads();

        #pragma unroll
        for (int kk = 0; kk < 8; kk++) {
            float4 xa = *reinterpret_cast<const float4*>(
                &sx[n0 * X_STRIDE + kk * 4]);
            float4 xb = *reinterpret_cast<const float4*>(
                &sx[n1 * X_STRIDE + kk * 4]);
            float xsa[4] = {xa.x, xa.y, xa.z, xa.w};
            float xsb[4] = {xb.x, xb.y, xb.z, xb.w};
            #pragma unroll
            for (int j = 0; j < 4; j++) {
                int k = chunk * 32 + kk * 4 + j;
                const ulonglong2* wp =
                    reinterpret_cast<const ulonglong2*>(sW + k * OUT_F);
                ull_t sa, sb;
                PACK_DUP_F32X2(sa, xsa[j]);
                PACK_DUP_F32X2(sb, xsb[j]);
                #pragma unroll
                for (int u = 0; u < 8; u++) {
                    ulonglong2 wv = wp[u];        // broadcast LDS.128, 1x per k
                    FMA_F32X2(acc0[2 * u + 0], sa, wv.x, acc0[2 * u + 0]);
                    FMA_F32X2(acc0[2 * u + 1], sa, wv.y, acc0[2 * u + 1]);
                    FMA_F32X2(acc1[2 * u + 0], sb, wv.x, acc1[2 * u + 0]);
                    FMA_F32X2(acc1[2 * u + 1], sb, wv.y, acc1[2 * u + 1]);
                }
            }
        }
    }

    // Store both z rows (fp16, 64B each, 4 STG.128).
    #pragma unroll
    for (int which = 0; which < 2; which++) {
        int node = base + (which ? n1 : n0);
        if (node >= n_nodes) continue;
        ull_t* acc = which ? acc1 : acc0;
        __half2 h[OUT_F / 2];
        #pragma unroll
        for (int o = 0; o < OUT_F / 2; o++) {
            float lo, hi;
            UNPACK_F32X2(lo, hi, acc[o]);
            h[o] = __floats2half2_rn(lo, hi);
        }
        uint4* zrow = reinterpret_cast<uint4*>(zh + (size_t)node * (OUT_F / 2));
        const uint4* hv = reinterpret_cast<const uint4*>(h);
        #pragma unroll
        for (int q = 0; q < 4; q++) zrow[q] = hv[q];
    }

    if (blockIdx.x == 0) {
        __syncthreads();
        if (tid == 0) g_idx64 = s_bad ? 0 : 1;
    }
}

// ---------------------------------------------------------------------------
// Edge kernel: 8 lanes per edge, uint2 (8B = 4 fp16) gathers -- 4 distinct
// z rows per gather warp-instruction (measured sweet spot). Each thread
// processes FOUR edges (m + q*E/4) with all index/val loads and all 8
// gathers front-batched: MLP=8 on the long-scoreboard path (R4 profile
// showed nothing saturated -> latency-exposed). Output: 1 STG.128 per lane
// per edge, coalesced, streaming.
// ---------------------------------------------------------------------------
__global__ __launch_bounds__(256)
void edge_kernel(const __half2* __restrict__ zh,
                 const int* __restrict__ rows,
                 const int* __restrict__ cols,
                 const float* __restrict__ vals,
                 float4* __restrict__ out,
                 int n_edges) {
    int gid = blockIdx.x * blockDim.x + threadIdx.x;
    int E4 = (n_edges + 3) >> 2;
    int m = gid >> 3;
    int c = gid & 7;
    if (m >= E4) return;

    int sh = g_idx64;           // 0: int32 layout, 1: int64 (read low word)

    int e[4];
    bool has[4];
    #pragma unroll
    for (int q = 0; q < 4; q++) {
        e[q] = m + q * E4;
        has[q] = (e[q] < n_edges);
    }

    int ri[4], ci[4];
    float wv[4];
    #pragma unroll
    for (int q = 0; q < 4; q++) {
        ri[q] = 0; ci[q] = 0; wv[q] = 0.f;
        if (has[q]) {
            ri[q] = __ldcs(&rows[e[q] << sh]);
            ci[q] = __ldcs(&cols[e[q] << sh]);
            wv[q] = __ldcs(&vals[e[q]]);
        }
    }

    const uint2* zb = reinterpret_cast<const uint2*>(zh);   // 8 uint2 per row
    uint2 ga[4], gd[4];
    #pragma unroll
    for (int q = 0; q < 4; q++) {
        ga[q] = make_uint2(0, 0);
        gd[q] = make_uint2(0, 0);
        if (has[q]) {
            ga[q] = __ldg(&zb[(size_t)ri[q] * 8 + c]);
            gd[q] = __ldg(&zb[(size_t)ci[q] * 8 + c]);
        }
    }

    #pragma unroll
    for (int q = 0; q < 4; q++) {
        if (!has[q]) continue;
        float2 fa0 = __half22float2(*reinterpret_cast<__half2*>(&ga[q].x));
        float2 fd0 = __half22float2(*reinterpret_cast<__half2*>(&gd[q].x));
        float2 fa1 = __half22float2(*reinterpret_cast<__half2*>(&ga[q].y));
        float2 fd1 = __half22float2(*reinterpret_cast<__half2*>(&gd[q].y));
        float4 o;
        o.x = wv[q] * (fa0.x + fd0.x);
        o.y = wv[q] * (fa0.y + fd0.y);
        o.z = wv[q] * (fa1.x + fd1.x);
        o.w = wv[q] * (fa1.y + fd1.y);
        __stcs(&out[(size_t)e[q] * 8 + c], o);
    }
}

// ---------------------------------------------------------------------------
// Launch. Inputs (metadata order): x, W, b, edge_rows, edge_cols, edge_vals.
// ---------------------------------------------------------------------------
extern "C" void kernel_launch(void* const* d_in, const int* in_sizes, int n_in,
                              void* d_out, int out_size) {
    const float4* x4   = (const float4*)d_in[0];
    const float*  W    = (const float*)d_in[1];
    const float*  b    = (const float*)d_in[2];
    const void*   rows = d_in[3];
    const void*   cols = d_in[4];
    const float*  vals = (const float*)d_in[5];
    float4* out = (float4*)d_out;

    int n_nodes = in_sizes[0] / IN_F;
    int n_edges = in_sizes[3];

    __half2* zh = nullptr;
    cudaGetSymbolAddress((void**)&zh, g_zh);

    // 1) z = x @ W + b  (+ index-dtype probe in block 0)
    int gemm_blocks = (n_nodes + NPB - 1) / NPB;
    gemm_kernel<<<gemm_blocks, GEMM_BLOCK>>>(
        x4, W, b, zh, n_nodes, (const long long*)rows);

    // 2) out[e] = w_e * (z[r] + z[c]), four edges per thread, 8 lanes/edge
    int E4 = (n_edges + 3) >> 2;
    long long total = (long long)E4 * 8;
    int edge_blocks = (int)((total + 255) / 256);
    edge_kernel<<<edge_blocks, 256>>>(zh, (const int*)rows, (const int*)cols,
                                      vals, out, n_edges);
}